// round 2
// baseline (speedup 1.0000x reference)
#include <cuda_runtime.h>

#define NH   448
#define NW   160
#define NPIX 71680          // NH*NW
#define PITCH 161           // smem activation pitch (odd -> conflict-free transpose)
#define A_BUF 20608         // 128*PITCH
#define A_THREADS 512
#define B_THREADS 256
#define W2PITCH 9           // padded j-pitch for W_cm2 staging

// ---- scratch (static device globals; no allocation) ----
__device__ float g_xr[(size_t)NPIX * 256];   // x_r rows, layout [(w*448+h)*256 + c]
__device__ int   g_inds[NPIX];               // argmax per (h,w), h-major

__device__ __forceinline__ float leaky_f(float v) { return v >= 0.f ? v : 0.01f * v; }

__device__ __forceinline__ void cp_async16(float* sdst, const float* gsrc) {
    unsigned saddr = (unsigned)__cvta_generic_to_shared(sdst);
    asm volatile("cp.async.cg.shared.global [%0], [%1], 16;" :: "r"(saddr), "l"(gsrc));
}

// issue cp.async for one 32-K weight chunk: Wg[o*128 + ci] -> wb[o*32 + ci], o in [0,128)
__device__ __forceinline__ void prefetch_chunk(float* __restrict__ wb,
                                               const float* __restrict__ Wg)
{
    for (int k = threadIdx.x; k < 1024; k += A_THREADS) {
        int o = k >> 3, seg = k & 7;                    // 8 x 16B segments per o-row
        cp_async16(wb + o * 32 + seg * 4, Wg + o * 128 + seg * 4);
    }
    asm volatile("cp.async.commit_group;");
}

// 128-out x 160-w x 128-c GEMM: in(smem,pitch161) * Wg(global,[o*128+c]) -> acc[8][5]
// thread tiling: o0 = (tid>>5)*8 (warp-uniform), w0 = (tid&31)*5
// wbuf: 2 x 4096 floats (double-buffered via cp.async)
__device__ __forceinline__ void gemm128(const float* __restrict__ in,
                                        const float* __restrict__ Wg,
                                        float* __restrict__ wbuf,
                                        int o0, int w0, float acc[8][5])
{
#pragma unroll
    for (int i = 0; i < 8; i++)
#pragma unroll
        for (int j = 0; j < 5; j++) acc[i][j] = 0.f;

    __syncthreads();                 // producer smem writes visible; wbuf free to overwrite
    prefetch_chunk(wbuf, Wg);        // chunk 0 -> buffer 0

    for (int cc = 0; cc < 128; cc += 32) {
        int cur = (cc >> 5) & 1;
        const float* wb = wbuf + cur * 4096;
        if (cc + 32 < 128) {
            prefetch_chunk(wbuf + (cur ^ 1) * 4096, Wg + cc + 32);
            asm volatile("cp.async.wait_group 1;");     // chunk cc landed
        } else {
            asm volatile("cp.async.wait_group 0;");
        }
        __syncthreads();             // all threads see chunk cc

        const float* inc = in + cc * PITCH + w0;
#pragma unroll
        for (int ci = 0; ci < 32; ci++) {
            float xv[5];
#pragma unroll
            for (int j = 0; j < 5; j++) xv[j] = inc[ci * PITCH + j];
#pragma unroll
            for (int i = 0; i < 8; i++) {
                float wv = wb[(o0 + i) * 32 + ci];      // warp-uniform broadcast
#pragma unroll
                for (int j = 0; j < 5; j++) acc[i][j] = fmaf(wv, xv[j], acc[i][j]);
            }
        }
        __syncthreads();             // done reading wb before it is re-prefetched
    }
}

extern "C" __global__ void __launch_bounds__(A_THREADS, 1)
stageA_kernel(const float* __restrict__ x_in,
              const float* __restrict__ Wcl1, const float* __restrict__ bcl1,
              const float* __restrict__ Wcl2, const float* __restrict__ bcl2,
              const float* __restrict__ Wcl3, const float* __restrict__ bcl3,
              const float* __restrict__ Wcl4, const float* __restrict__ bcl4,
              const float* __restrict__ Wreg1, const float* __restrict__ breg1,
              float* __restrict__ out)
{
    extern __shared__ float sm[];
    float* bufA = sm;                       // 128*PITCH
    float* bufB = sm + A_BUF;               // 128*PITCH
    float* wbuf = sm + 2 * A_BUF;           // 2*4096 (double buffer)
    float* best = wbuf + 8192;              // 160
    int*   bestI = (int*)(best + NW);       // 160

    const int h   = blockIdx.x;
    const int tid = threadIdx.x;
    const int o0  = (tid >> 5) * 8;
    const int w0  = (tid & 31) * 5;
    const int warp = tid >> 5, lane = tid & 31;

    // load x tile: x_in[c*NPIX + h*NW + w] -> bufA[c*PITCH + w]
    for (int idx = tid; idx < 128 * NW; idx += A_THREADS) {
        int c = idx / NW, w = idx - c * NW;
        bufA[c * PITCH + w] = x_in[c * NPIX + h * NW + w];
    }
    // (visibility covered by gemm128's entry __syncthreads)

    float acc[8][5];

    // ---- reg1: 256 outputs in two 128-halves, leaky, write g_xr (transposed via bufB) ----
    for (int half = 0; half < 2; half++) {
        const float* Wg = Wreg1 + ((size_t)h * 256 + half * 128) * 128;
        const float* bg = breg1 + h * 256 + half * 128;
        gemm128(bufA, Wg, wbuf, o0, w0, acc);
#pragma unroll
        for (int i = 0; i < 8; i++) {
            float b = bg[o0 + i];
#pragma unroll
            for (int j = 0; j < 5; j++)
                bufB[(o0 + i) * PITCH + w0 + j] = leaky_f(acc[i][j] + b);
        }
        __syncthreads();
        // transposed, coalesced write: g_xr[(w*448+h)*256 + half*128 + k]
        for (int w = warp; w < NW; w += 16) {
            float* dst = g_xr + ((size_t)(w * NH + h)) * 256 + half * 128;
            for (int k = lane; k < 128; k += 32)
                dst[k] = bufB[k * PITCH + w];    // bank-conflict-free (pitch 161)
        }
    }

    // ---- cl1: bufA -> bufB ----
    {
        gemm128(bufA, Wcl1 + (size_t)h * 16384, wbuf, o0, w0, acc);
        const float* bg = bcl1 + h * 128;
#pragma unroll
        for (int i = 0; i < 8; i++) { float b = bg[o0 + i];
#pragma unroll
            for (int j = 0; j < 5; j++) bufB[(o0 + i) * PITCH + w0 + j] = leaky_f(acc[i][j] + b); }
    }
    // ---- cl2: bufB -> bufA ----
    {
        gemm128(bufB, Wcl2 + (size_t)h * 16384, wbuf, o0, w0, acc);
        const float* bg = bcl2 + h * 128;
#pragma unroll
        for (int i = 0; i < 8; i++) { float b = bg[o0 + i];
#pragma unroll
            for (int j = 0; j < 5; j++) bufA[(o0 + i) * PITCH + w0 + j] = leaky_f(acc[i][j] + b); }
    }
    // ---- cl3: bufA -> bufB ----
    {
        gemm128(bufA, Wcl3 + (size_t)h * 16384, wbuf, o0, w0, acc);
        const float* bg = bcl3 + h * 128;
#pragma unroll
        for (int i = 0; i < 8; i++) { float b = bg[o0 + i];
#pragma unroll
            for (int j = 0; j < 5; j++) bufB[(o0 + i) * PITCH + w0 + j] = leaky_f(acc[i][j] + b); }
    }

    // ---- cl4: 256 class logits (two halves, staged in bufA) + argmax ----
    if (tid < NW) { best[tid] = -3.402823466e38f; bestI[tid] = 0; }

    for (int half = 0; half < 2; half++) {
        const float* Wg = Wcl4 + ((size_t)h * 257 + half * 128) * 128;
        const float* bg = bcl4 + h * 257 + half * 128;
        gemm128(bufB, Wg, wbuf, o0, w0, acc);   // input = h3 in bufB
#pragma unroll
        for (int i = 0; i < 8; i++) { float b = bg[o0 + i];
#pragma unroll
            for (int j = 0; j < 5; j++) bufA[(o0 + i) * PITCH + w0 + j] = acc[i][j] + b; }
        __syncthreads();
        if (tid < NW) {   // ascending o + strict '>' == jnp.argmax first-max semantics
            float bm = best[tid]; int bi = bestI[tid];
            for (int o = 0; o < 128; o++) {
                float v = bufA[o * PITCH + tid];
                if (v > bm) { bm = v; bi = half * 128 + o; }
            }
            best[tid] = bm; bestI[tid] = bi;
        }
        __syncthreads();
    }

    // ---- mask row (o = 256) ----
    if (tid < 128) wbuf[tid] = Wcl4[((size_t)h * 257 + 256) * 128 + tid];
    __syncthreads();
    if (tid < NW) {
        float s = bcl4[h * 257 + 256];
        for (int c = 0; c < 128; c++) s = fmaf(wbuf[c], bufB[c * PITCH + tid], s);
        out[NPIX + h * NW + tid] = leaky_f(s);   // mask = leaky(logit[256])
        g_inds[h * NW + tid] = bestI[tid];
    }
}

// ---- stage B: gathered cm2/cm3 regression head ----
// n in [h2*160, h2*160+160): xr row at (w=n/448, h=n%448); sc/ic indices from (h2=n/160, w2=n%160)
extern "C" __global__ void __launch_bounds__(B_THREADS, 1)
stageB_kernel(const float* __restrict__ Wcm2, const float* __restrict__ bcm2,
              const float* __restrict__ Wcm3, const float* __restrict__ bcm3,
              float* __restrict__ out)
{
    extern __shared__ float sm[];
    float* ws2 = sm;                           // 16 * 256 * W2PITCH
    float* w3s = ws2 + 16 * 256 * W2PITCH;     // 256*8
    float* b2s = w3s + 2048;                   // 128
    float* b3s = b2s + 128;                    // 256
    int*   indsRow = (int*)(b3s + 256);        // 160

    const int h2  = blockIdx.x;
    const int tid = threadIdx.x;
    const int lane = tid & 31, warp = tid >> 5;

    // stage the 16 candidate W_cm2 [256 x 8] matrices (padded pitch 9 -> conflict-free)
    {
        const float* src = Wcm2 + (size_t)h2 * 16 * 2048;
        for (int idx = tid; idx < 32768; idx += B_THREADS) {
            int s = idx >> 11, rem = idx & 2047;
            int c = rem >> 3,  j  = rem & 7;
            ws2[s * (256 * W2PITCH) + c * W2PITCH + j] = src[idx];
        }
    }
    for (int idx = tid; idx < 2048; idx += B_THREADS) w3s[idx] = Wcm3[(size_t)h2 * 2048 + idx];
    if (tid < 128) b2s[tid] = bcm2[h2 * 128 + tid];
    b3s[tid] = bcm3[h2 * 256 + tid];           // B_THREADS=256 covers all
    if (tid < NW)  indsRow[tid] = g_inds[h2 * NW + tid];
    __syncthreads();

    for (int nl = warp; nl < NW; nl += (B_THREADS / 32)) {
        int n   = h2 * NW + nl;
        int ind = indsRow[nl];
        int s   = ind >> 4;                    // ind / CLASS_FACTOR
        const float* xr = g_xr + (size_t)n * 256;
        const float* w2 = ws2 + s * (256 * W2PITCH);

        float acc[8];
#pragma unroll
        for (int j = 0; j < 8; j++) acc[j] = 0.f;
#pragma unroll
        for (int k = 0; k < 8; k++) {
            int c = lane + 32 * k;
            float xv = xr[c];                  // coalesced
            const float* wr = w2 + c * W2PITCH;
#pragma unroll
            for (int j = 0; j < 8; j++) acc[j] = fmaf(xv, wr[j], acc[j]);
        }
#pragma unroll
        for (int off = 16; off; off >>= 1)
#pragma unroll
            for (int j = 0; j < 8; j++) acc[j] += __shfl_xor_sync(0xffffffffu, acc[j], off);

        if (lane == 0) {
            float r = b3s[ind];
#pragma unroll
            for (int j = 0; j < 8; j++) {
                float y = acc[j] + b2s[s * 8 + j];
                y = y >= 0.f ? y : 0.01f * y;
                r = fmaf(y, w3s[ind * 8 + j], r);
            }
            int hh = n % NH, ww = n / NH;
            int opos = hh * NW + ww;           // output at (h,w); adds inds AT the output location
            out[opos] = ((float)g_inds[opos] + r) * (1.0f / 256.0f);
        }
    }
}

extern "C" void kernel_launch(void* const* d_in, const int* in_sizes, int n_in,
                              void* d_out, int out_size)
{
    const float* x_in  = (const float*)d_in[0];
    const float* Wcl1  = (const float*)d_in[1];
    const float* bcl1  = (const float*)d_in[2];
    const float* Wcl2  = (const float*)d_in[3];
    const float* bcl2  = (const float*)d_in[4];
    const float* Wcl3  = (const float*)d_in[5];
    const float* bcl3  = (const float*)d_in[6];
    const float* Wcl4  = (const float*)d_in[7];
    const float* bcl4  = (const float*)d_in[8];
    const float* Wreg1 = (const float*)d_in[9];
    const float* breg1 = (const float*)d_in[10];
    const float* Wcm2  = (const float*)d_in[11];
    const float* bcm2  = (const float*)d_in[12];
    const float* Wcm3  = (const float*)d_in[13];
    const float* bcm3  = (const float*)d_in[14];
    float* out = (float*)d_out;

    const int smemA = (2 * A_BUF + 8192 + NW) * 4 + NW * 4;                  // ~194 KB
    const int smemB = (16 * 256 * W2PITCH + 2048 + 128 + 256) * 4 + NW * 4;  // ~154 KB
    cudaFuncSetAttribute(stageA_kernel, cudaFuncAttributeMaxDynamicSharedMemorySize, smemA);
    cudaFuncSetAttribute(stageB_kernel, cudaFuncAttributeMaxDynamicSharedMemorySize, smemB);

    stageA_kernel<<<NH, A_THREADS, smemA>>>(x_in, Wcl1, bcl1, Wcl2, bcl2, Wcl3, bcl3,
                                            Wcl4, bcl4, Wreg1, breg1, out);
    stageB_kernel<<<NH, B_THREADS, smemB>>>(Wcm2, bcm2, Wcm3, bcm3, out);
}

// round 3
// speedup vs baseline: 1.3331x; 1.3331x over previous
#include <cuda_runtime.h>
#include <cstdint>

#define NH   448
#define NW   160
#define NPIX 71680          // NH*NW
#define PITCH 162           // even: 8B-aligned rows for ld.shared.b64
#define A_BUF (128*PITCH)   // 20736 floats
#define A_THREADS 512
#define B_THREADS 1024
#define WP   36             // weight smem pitch (floats): 144B rows, 16B-aligned
#define WBUF (128*WP)       // 4608 floats per buffer
#define W2PITCH 9           // padded j-pitch for W_cm2 staging

// ---- scratch (static device globals; no allocation) ----
__device__ float g_xr[(size_t)NPIX * 256];   // x_r rows, layout [(w*448+h)*256 + c]
__device__ int   g_inds[NPIX];               // argmax per (h,w), h-major

__device__ __forceinline__ float leaky_f(float v) { return v >= 0.f ? v : 0.01f * v; }

__device__ __forceinline__ void cp_async16(uint32_t saddr, const float* gsrc) {
    asm volatile("cp.async.cg.shared.global [%0], [%1], 16;" :: "r"(saddr), "l"(gsrc));
}
__device__ __forceinline__ uint64_t lds64(uint32_t addr) {
    uint64_t v; asm volatile("ld.shared.b64 %0, [%1];" : "=l"(v) : "r"(addr)); return v;
}
__device__ __forceinline__ uint32_t lds32(uint32_t addr) {
    uint32_t v; asm volatile("ld.shared.b32 %0, [%1];" : "=r"(v) : "r"(addr)); return v;
}
__device__ __forceinline__ uint64_t dup2(uint32_t w) {
    uint64_t v; asm("mov.b64 %0, {%1, %1};" : "=l"(v) : "r"(w)); return v;
}
__device__ __forceinline__ void fma2(uint64_t& d, uint64_t a, uint64_t b) {
    asm("fma.rn.f32x2 %0, %1, %2, %0;" : "+l"(d) : "l"(a), "l"(b));
}
__device__ __forceinline__ float lo_f(uint64_t v) { return __uint_as_float((uint32_t)v); }
__device__ __forceinline__ float hi_f(uint64_t v) { return __uint_as_float((uint32_t)(v >> 32)); }

// issue cp.async for one 32-K weight chunk: Wg[o*128 + ci] -> wb[o*WP + ci] (ci 0..31)
__device__ __forceinline__ void prefetch_chunk(uint32_t wb_a, const float* __restrict__ Wg)
{
    for (int k = threadIdx.x; k < 1024; k += A_THREADS) {
        int o = k >> 3, seg = k & 7;                    // 8 x 16B segments per o-row
        cp_async16(wb_a + (o * WP + seg * 4) * 4, Wg + o * 128 + seg * 4);
    }
    asm volatile("cp.async.commit_group;");
}

// 128-out x 160-w x 128-c GEMM with packed f32x2 math.
// in: smem activations [c*PITCH + w]; Wg: global [o*128 + c]; wbuf: 2 x WBUF floats.
// thread tiling: o0 = ((warp<<1)|(lane>>4))*4, w0 = (lane&15)*10 (5 f32x2 pairs)
__device__ __forceinline__ void gemm128(uint32_t in_a, const float* __restrict__ Wg,
                                        uint32_t wb_a, int o0, int w0,
                                        uint64_t acc[4][5])
{
#pragma unroll
    for (int i = 0; i < 4; i++)
#pragma unroll
        for (int j = 0; j < 5; j++) acc[i][j] = 0ull;

    __syncthreads();                 // producer smem writes visible; wbuf free to overwrite
    prefetch_chunk(wb_a, Wg);        // chunk 0 -> buffer 0

    for (int cc = 0; cc < 128; cc += 32) {
        int cur = (cc >> 5) & 1;
        uint32_t wb = wb_a + cur * (WBUF * 4);
        if (cc + 32 < 128) {
            prefetch_chunk(wb_a + (cur ^ 1) * (WBUF * 4), Wg + cc + 32);
            asm volatile("cp.async.wait_group 1;");     // chunk cc landed
        } else {
            asm volatile("cp.async.wait_group 0;");
        }
        __syncthreads();             // all threads see chunk cc

        uint32_t xa = in_a + (cc * PITCH + w0) * 4;
        uint32_t wa = wb + o0 * (WP * 4);
#pragma unroll 4
        for (int ci = 0; ci < 32; ci++) {
            uint64_t xv[5];
#pragma unroll
            for (int j = 0; j < 5; j++) xv[j] = lds64(xa + j * 8);
#pragma unroll
            for (int i = 0; i < 4; i++) {
                uint64_t wp = dup2(lds32(wa + i * (WP * 4)));   // broadcast (w,w)
#pragma unroll
                for (int j = 0; j < 5; j++) fma2(acc[i][j], wp, xv[j]);
            }
            xa += PITCH * 4;
            wa += 4;
        }
        __syncthreads();             // done reading wb before it is re-prefetched
    }
}

extern "C" __global__ void __launch_bounds__(A_THREADS, 1)
stageA_kernel(const float* __restrict__ x_in,
              const float* __restrict__ Wcl1, const float* __restrict__ bcl1,
              const float* __restrict__ Wcl2, const float* __restrict__ bcl2,
              const float* __restrict__ Wcl3, const float* __restrict__ bcl3,
              const float* __restrict__ Wcl4, const float* __restrict__ bcl4,
              const float* __restrict__ Wreg1, const float* __restrict__ breg1,
              float* __restrict__ out)
{
    extern __shared__ float sm[];
    float* bufA = sm;                       // A_BUF
    float* bufB = sm + A_BUF;               // A_BUF
    float* wbuf = sm + 2 * A_BUF;           // 2*WBUF (double buffer)
    float* best = wbuf + 2 * WBUF;          // 160
    int*   bestI = (int*)(best + NW);       // 160

    const uint32_t sbase = (uint32_t)__cvta_generic_to_shared(sm);
    const uint32_t bufA_a = sbase;
    const uint32_t bufB_a = sbase + A_BUF * 4;
    const uint32_t wbuf_a = sbase + 2 * A_BUF * 4;

    const int h    = blockIdx.x;
    const int tid  = threadIdx.x;
    const int warp = tid >> 5, lane = tid & 31;
    const int o0   = (((warp << 1) | (lane >> 4)) << 2);   // 0..124 step 4
    const int w0   = (lane & 15) * 10;                     // 0..150 step 10

    // load x tile: x_in[c*NPIX + h*NW + w] -> bufA[c*PITCH + w]
    for (int idx = tid; idx < 128 * NW; idx += A_THREADS) {
        int c = idx / NW, w = idx - c * NW;
        bufA[c * PITCH + w] = x_in[c * NPIX + h * NW + w];
    }
    // (visibility covered by gemm128's entry __syncthreads)

    uint64_t acc[4][5];

    // ---- reg1: 256 outputs in two 128-halves, leaky, write g_xr (transposed via bufB) ----
    for (int half = 0; half < 2; half++) {
        const float* Wg = Wreg1 + ((size_t)h * 256 + half * 128) * 128;
        const float* bg = breg1 + h * 256 + half * 128;
        gemm128(bufA_a, Wg, wbuf_a, o0, w0, acc);
#pragma unroll
        for (int i = 0; i < 4; i++) {
            float b = bg[o0 + i];
            float* dst = bufB + (o0 + i) * PITCH + w0;
#pragma unroll
            for (int j = 0; j < 5; j++) {
                dst[2 * j]     = leaky_f(lo_f(acc[i][j]) + b);
                dst[2 * j + 1] = leaky_f(hi_f(acc[i][j]) + b);
            }
        }
        __syncthreads();
        // transposed, coalesced write: g_xr[(w*448+h)*256 + half*128 + k]
        for (int w = warp; w < NW; w += 16) {
            float* dst = g_xr + ((size_t)(w * NH + h)) * 256 + half * 128;
            for (int k = lane; k < 128; k += 32)
                dst[k] = bufB[k * PITCH + w];
        }
    }

#define EPILOGUE(DST, BG, ACT)                                               \
    {                                                                        \
        const float* bg = (BG);                                              \
        _Pragma("unroll")                                                    \
        for (int i = 0; i < 4; i++) {                                        \
            float b = bg[o0 + i];                                            \
            float* dst = (DST) + (o0 + i) * PITCH + w0;                      \
            _Pragma("unroll")                                                \
            for (int j = 0; j < 5; j++) {                                    \
                float v0 = lo_f(acc[i][j]) + b, v1 = hi_f(acc[i][j]) + b;    \
                dst[2 * j]     = ACT(v0);                                    \
                dst[2 * j + 1] = ACT(v1);                                    \
            }                                                                \
        }                                                                    \
    }
#define IDF(v) (v)

    // ---- cl1: bufA -> bufB ----
    gemm128(bufA_a, Wcl1 + (size_t)h * 16384, wbuf_a, o0, w0, acc);
    EPILOGUE(bufB, bcl1 + h * 128, leaky_f)
    // ---- cl2: bufB -> bufA ----
    gemm128(bufB_a, Wcl2 + (size_t)h * 16384, wbuf_a, o0, w0, acc);
    EPILOGUE(bufA, bcl2 + h * 128, leaky_f)
    // ---- cl3: bufA -> bufB ----
    gemm128(bufA_a, Wcl3 + (size_t)h * 16384, wbuf_a, o0, w0, acc);
    EPILOGUE(bufB, bcl3 + h * 128, leaky_f)

    // ---- cl4: 256 class logits (two halves, staged in bufA) + argmax ----
    if (tid < NW) { best[tid] = -3.402823466e38f; bestI[tid] = 0; }

    for (int half = 0; half < 2; half++) {
        const float* Wg = Wcl4 + ((size_t)h * 257 + half * 128) * 128;
        gemm128(bufB_a, Wg, wbuf_a, o0, w0, acc);   // input = h3 in bufB
        EPILOGUE(bufA, bcl4 + h * 257 + half * 128, IDF)
        __syncthreads();
        if (tid < NW) {   // ascending o + strict '>' == jnp.argmax first-max semantics
            float bm = best[tid]; int bi = bestI[tid];
            for (int o = 0; o < 128; o++) {
                float v = bufA[o * PITCH + tid];
                if (v > bm) { bm = v; bi = half * 128 + o; }
            }
            best[tid] = bm; bestI[tid] = bi;
        }
        __syncthreads();
    }

    // ---- mask row (o = 256) ----
    if (tid < 128) wbuf[tid] = Wcl4[((size_t)h * 257 + 256) * 128 + tid];
    __syncthreads();
    if (tid < NW) {
        float s = bcl4[h * 257 + 256];
        for (int c = 0; c < 128; c++) s = fmaf(wbuf[c], bufB[c * PITCH + tid], s);
        out[NPIX + h * NW + tid] = leaky_f(s);   // mask = leaky(logit[256])
        g_inds[h * NW + tid] = bestI[tid];
    }
}

// ---- stage B: gathered cm2/cm3 regression head ----
// n in [h2*160, h2*160+160): xr row at (w=n/448, h=n%448); sc/ic indices from (h2=n/160, w2=n%160)
extern "C" __global__ void __launch_bounds__(B_THREADS, 1)
stageB_kernel(const float* __restrict__ Wcm2, const float* __restrict__ bcm2,
              const float* __restrict__ Wcm3, const float* __restrict__ bcm3,
              float* __restrict__ out)
{
    extern __shared__ float sm[];
    float* ws2 = sm;                           // 16 * 256 * W2PITCH
    float* w3s = ws2 + 16 * 256 * W2PITCH;     // 256*8
    float* b2s = w3s + 2048;                   // 128
    float* b3s = b2s + 128;                    // 256
    int*   indsRow = (int*)(b3s + 256);        // 160

    const int h2  = blockIdx.x;
    const int tid = threadIdx.x;
    const int lane = tid & 31, warp = tid >> 5;

    // stage the 16 candidate W_cm2 [256 x 8] matrices (padded pitch 9 -> conflict-free)
    {
        const float* src = Wcm2 + (size_t)h2 * 16 * 2048;
        for (int idx = tid; idx < 32768; idx += B_THREADS) {
            int s = idx >> 11, rem = idx & 2047;
            int c = rem >> 3,  j  = rem & 7;
            ws2[s * (256 * W2PITCH) + c * W2PITCH + j] = src[idx];
        }
    }
    for (int idx = tid; idx < 2048; idx += B_THREADS) w3s[idx] = Wcm3[(size_t)h2 * 2048 + idx];
    if (tid < 128) b2s[tid] = bcm2[h2 * 128 + tid];
    if (tid < 256) b3s[tid] = bcm3[h2 * 256 + tid];
    if (tid < NW)  indsRow[tid] = g_inds[h2 * NW + tid];
    __syncthreads();

    for (int nl = warp; nl < NW; nl += (B_THREADS / 32)) {
        int n   = h2 * NW + nl;
        int ind = indsRow[nl];
        int s   = ind >> 4;                    // ind / CLASS_FACTOR
        const float* xr = g_xr + (size_t)n * 256;
        const float* w2 = ws2 + s * (256 * W2PITCH);

        float acc[8];
#pragma unroll
        for (int j = 0; j < 8; j++) acc[j] = 0.f;
#pragma unroll
        for (int k = 0; k < 8; k++) {
            int c = lane + 32 * k;
            float xv = xr[c];                  // coalesced
            const float* wr = w2 + c * W2PITCH;
#pragma unroll
            for (int j = 0; j < 8; j++) acc[j] = fmaf(xv, wr[j], acc[j]);
        }
#pragma unroll
        for (int off = 16; off; off >>= 1)
#pragma unroll
            for (int j = 0; j < 8; j++) acc[j] += __shfl_xor_sync(0xffffffffu, acc[j], off);

        if (lane == 0) {
            float r = b3s[ind];
#pragma unroll
            for (int j = 0; j < 8; j++) {
                float y = acc[j] + b2s[s * 8 + j];
                y = y >= 0.f ? y : 0.01f * y;
                r = fmaf(y, w3s[ind * 8 + j], r);
            }
            int hh = n % NH, ww = n / NH;
            int opos = hh * NW + ww;           // output at (h,w); adds inds AT the output location
            out[opos] = ((float)g_inds[opos] + r) * (1.0f / 256.0f);
        }
    }
}

extern "C" void kernel_launch(void* const* d_in, const int* in_sizes, int n_in,
                              void* d_out, int out_size)
{
    const float* x_in  = (const float*)d_in[0];
    const float* Wcl1  = (const float*)d_in[1];
    const float* bcl1  = (const float*)d_in[2];
    const float* Wcl2  = (const float*)d_in[3];
    const float* bcl2  = (const float*)d_in[4];
    const float* Wcl3  = (const float*)d_in[5];
    const float* bcl3  = (const float*)d_in[6];
    const float* Wcl4  = (const float*)d_in[7];
    const float* bcl4  = (const float*)d_in[8];
    const float* Wreg1 = (const float*)d_in[9];
    const float* breg1 = (const float*)d_in[10];
    const float* Wcm2  = (const float*)d_in[11];
    const float* bcm2  = (const float*)d_in[12];
    const float* Wcm3  = (const float*)d_in[13];
    const float* bcm3  = (const float*)d_in[14];
    float* out = (float*)d_out;

    const int smemA = (2 * A_BUF + 2 * WBUF + NW) * 4 + NW * 4;              // ~204 KB
    const int smemB = (16 * 256 * W2PITCH + 2048 + 128 + 256) * 4 + NW * 4;  // ~154 KB
    cudaFuncSetAttribute(stageA_kernel, cudaFuncAttributeMaxDynamicSharedMemorySize, smemA);
    cudaFuncSetAttribute(stageB_kernel, cudaFuncAttributeMaxDynamicSharedMemorySize, smemB);

    stageA_kernel<<<NH, A_THREADS, smemA>>>(x_in, Wcl1, bcl1, Wcl2, bcl2, Wcl3, bcl3,
                                            Wcl4, bcl4, Wreg1, breg1, out);
    stageB_kernel<<<NH, B_THREADS, smemB>>>(Wcm2, bcm2, Wcm3, bcm3, out);
}